// round 5
// baseline (speedup 1.0000x reference)
#include <cuda_runtime.h>
#include <cstdint>

#define E_N 100000
#define T_N 400000
#define D_N 128

// Scratch: segment accumulator + counts (device globals — no runtime alloc).
__device__ float g_seg[(long long)E_N * D_N];
__device__ float g_cnt[E_N];

// ---------------------------------------------------------------------------
// helpers
// ---------------------------------------------------------------------------
__device__ __forceinline__ uint32_t f2tf(float f) {
    uint32_t o;
    asm("cvt.rna.tf32.f32 %0, %1;" : "=r"(o) : "f"(f));
    return o;
}

__device__ __forceinline__ void mma8(float c[4], const uint32_t a[4],
                                     uint32_t b0, uint32_t b1) {
    asm volatile(
        "mma.sync.aligned.m16n8k8.row.col.f32.tf32.tf32.f32 "
        "{%0,%1,%2,%3}, {%4,%5,%6,%7}, {%8,%9}, {%0,%1,%2,%3};\n"
        : "+f"(c[0]), "+f"(c[1]), "+f"(c[2]), "+f"(c[3])
        : "r"(a[0]), "r"(a[1]), "r"(a[2]), "r"(a[3]), "r"(b0), "r"(b1));
}

__device__ __forceinline__ void red2(float* p, float x, float y) {
    asm volatile("red.global.add.v2.f32 [%0], {%1,%2};"
                 :: "l"(p), "f"(x), "f"(y) : "memory");
}

__device__ __forceinline__ float gelu_exact(float x) {
    return 0.5f * x * (1.0f + erff(x * 0.70710678118654752f));
}

// ---------------------------------------------------------------------------
// kernel 0: zero the scratch
// ---------------------------------------------------------------------------
__global__ void zero_kernel() {
    long long i = (long long)blockIdx.x * blockDim.x + threadIdx.x;
    const long long tot = (long long)E_N * D_N;
    if (i < tot) g_seg[i] = 0.0f;
    if (i < E_N) g_cnt[i] = 0.0f;
}

// ---------------------------------------------------------------------------
// kernel 1: fused gather + tf32 GEMM + bias + GELU + segment scatter-add
//   BM=128 triangles/block, BN=128 (full D), K=384 in 12 chunks of 32.
//   8 warps: 4 (M) x 2 (N); warp tile 32x64; m16n8k8 tf32 mma.
// ---------------------------------------------------------------------------
__global__ __launch_bounds__(256, 2)
void tri_gemm_kernel(const float* __restrict__ f_edge,
                     const float* __restrict__ W,
                     const float* __restrict__ bias,
                     const int* __restrict__ tri) {     // int32 (jax x64 off)
    __shared__ uint32_t sA[128 * 36];   // 128 rows x 32 k, pad stride 36
    __shared__ uint32_t sB[32 * 136];   // 32 k x 128 n, pad stride 136
    __shared__ int sIdx[128][3];
    __shared__ float sBias[128];

    const int tid = threadIdx.x;
    const int t0 = blockIdx.x * 128;   // T = 400000 = 3125 * 128, no ragged tile

    // triangle indices for this tile
    for (int i = tid; i < 384; i += 256) {
        int r = i / 3, j = i % 3;
        sIdx[r][j] = tri[(long long)(t0 + r) * 3 + j];
    }
    if (tid < 128) sBias[tid] = bias[tid];
    __syncthreads();

    // per-triangle count contribution (once per block-tile row)
    if (tid < 128) atomicAdd(&g_cnt[sIdx[tid][2]], 1.0f);

    const int lane  = tid & 31;
    const int warp  = tid >> 5;
    const int warpM = warp & 3;    // 0..3 -> rows warpM*32
    const int warpN = warp >> 2;   // 0..1 -> cols warpN*64
    const int gid   = lane >> 2;   // groupID (0..7)
    const int t4    = lane & 3;    // threadID_in_group (0..3)

    float acc[2][8][4];
#pragma unroll
    for (int a = 0; a < 2; ++a)
#pragma unroll
        for (int b = 0; b < 8; ++b)
#pragma unroll
            for (int c = 0; c < 4; ++c) acc[a][b][c] = 0.0f;

    for (int ch = 0; ch < 12; ++ch) {
        const int j   = ch >> 2;          // which of the 3 gathered edges
        const int off = (ch & 3) * 32;    // k-offset within that edge's 128

        __syncthreads();
        // A tile: 128 rows x 32 floats = 1024 float4 loads (gathered)
#pragma unroll
        for (int i = 0; i < 4; ++i) {
            int fid = tid + i * 256;
            int r = fid >> 3;
            int q = (fid & 7) * 4;
            float4 v = *reinterpret_cast<const float4*>(
                f_edge + (long long)sIdx[r][j] * 128 + off + q);
            uint32_t* d = &sA[r * 36 + q];
            d[0] = f2tf(v.x); d[1] = f2tf(v.y); d[2] = f2tf(v.z); d[3] = f2tf(v.w);
        }
        // B tile: W rows [ch*32, ch*32+32) x 128 cols
#pragma unroll
        for (int i = 0; i < 4; ++i) {
            int fid = tid + i * 256;
            int r = fid >> 5;
            int q = (fid & 31) * 4;
            float4 v = *reinterpret_cast<const float4*>(
                W + (long long)(ch * 32 + r) * 128 + q);
            uint32_t* d = &sB[r * 136 + q];
            d[0] = f2tf(v.x); d[1] = f2tf(v.y); d[2] = f2tf(v.z); d[3] = f2tf(v.w);
        }
        __syncthreads();

#pragma unroll
        for (int kk = 0; kk < 4; ++kk) {
            const int k0 = kk * 8;
            uint32_t afr[2][4];
#pragma unroll
            for (int mt = 0; mt < 2; ++mt) {
                int rb = warpM * 32 + mt * 16 + gid;
                afr[mt][0] = sA[rb * 36 + k0 + t4];
                afr[mt][1] = sA[(rb + 8) * 36 + k0 + t4];
                afr[mt][2] = sA[rb * 36 + k0 + t4 + 4];
                afr[mt][3] = sA[(rb + 8) * 36 + k0 + t4 + 4];
            }
#pragma unroll
            for (int nt = 0; nt < 8; ++nt) {
                int nb = warpN * 64 + nt * 8 + gid;
                uint32_t b0 = sB[(k0 + t4) * 136 + nb];
                uint32_t b1 = sB[(k0 + t4 + 4) * 136 + nb];
                mma8(acc[0][nt], afr[0], b0, b1);
                mma8(acc[1][nt], afr[1], b0, b1);
            }
        }
    }

    // Epilogue: bias + exact GELU + vectorized reduction into g_seg
#pragma unroll
    for (int mt = 0; mt < 2; ++mt) {
        int r0 = warpM * 32 + mt * 16 + gid;
        int dst0 = sIdx[r0][2];
        int dst1 = sIdx[r0 + 8][2];
        float* p0 = g_seg + (long long)dst0 * 128;
        float* p1 = g_seg + (long long)dst1 * 128;
#pragma unroll
        for (int nt = 0; nt < 8; ++nt) {
            int c0 = warpN * 64 + nt * 8 + t4 * 2;
            float bv0 = sBias[c0], bv1 = sBias[c0 + 1];
            float x0 = gelu_exact(acc[mt][nt][0] + bv0);
            float x1 = gelu_exact(acc[mt][nt][1] + bv1);
            float x2 = gelu_exact(acc[mt][nt][2] + bv0);
            float x3 = gelu_exact(acc[mt][nt][3] + bv1);
            red2(p0 + c0, x0, x1);
            red2(p1 + c0, x2, x3);
        }
    }
}

// ---------------------------------------------------------------------------
// kernel 2: segment mean + layernorm. One warp per edge, 4 cols/lane.
// ---------------------------------------------------------------------------
__global__ __launch_bounds__(256)
void ln_kernel(const float* __restrict__ gamma,
               const float* __restrict__ beta,
               float* __restrict__ out) {
    const int warp = threadIdx.x >> 5;
    const int lane = threadIdx.x & 31;
    const int e = blockIdx.x * 8 + warp;   // E = 100000 = 12500 * 8
    if (e >= E_N) return;

    const float inv = 1.0f / fmaxf(g_cnt[e], 1.0f);
    const long long base = (long long)e * 128;

    float m[4];
    float s = 0.0f;
#pragma unroll
    for (int i = 0; i < 4; ++i) {
        m[i] = g_seg[base + lane + 32 * i] * inv;
        s += m[i];
    }
#pragma unroll
    for (int o = 16; o; o >>= 1) s += __shfl_xor_sync(0xffffffffu, s, o);
    const float mu = s * (1.0f / 128.0f);

    float v = 0.0f;
#pragma unroll
    for (int i = 0; i < 4; ++i) {
        float d = m[i] - mu;
        v += d * d;
    }
#pragma unroll
    for (int o = 16; o; o >>= 1) v += __shfl_xor_sync(0xffffffffu, v, o);
    const float rstd = rsqrtf(v * (1.0f / 128.0f) + 1e-5f);

#pragma unroll
    for (int i = 0; i < 4; ++i) {
        int c = lane + 32 * i;
        out[base + c] = (m[i] - mu) * rstd * gamma[c] + beta[c];
    }
}

// ---------------------------------------------------------------------------
extern "C" void kernel_launch(void* const* d_in, const int* in_sizes, int n_in,
                              void* d_out, int out_size) {
    // Resolve inputs by element count (robust to metadata ordering):
    //   f_edge: E*D = 12,800,000   W: 384*128 = 49,152
    //   triangle: T*3 = 1,200,000  b/gamma/beta: 128 each (in that order)
    const float* f_edge = nullptr;
    const float* W      = nullptr;
    const int*   tri    = nullptr;
    const float* vec128[3] = {nullptr, nullptr, nullptr};
    int nv = 0;
    for (int i = 0; i < n_in; ++i) {
        long long sz = in_sizes[i];
        if (sz == (long long)E_N * D_N)      f_edge = (const float*)d_in[i];
        else if (sz == 3LL * D_N * D_N)      W      = (const float*)d_in[i];
        else if (sz == 3LL * T_N)            tri    = (const int*)d_in[i];
        else if (sz == D_N && nv < 3)        vec128[nv++] = (const float*)d_in[i];
    }
    const float* b     = vec128[0];
    const float* gamma = vec128[1];
    const float* beta  = vec128[2];
    float* out = (float*)d_out;

    // 12.8M elements / 256 = 50000 blocks (covers both g_seg and g_cnt)
    zero_kernel<<<50000, 256>>>();
    tri_gemm_kernel<<<T_N / 128, 256>>>(f_edge, W, b, tri);
    ln_kernel<<<E_N / 8, 256>>>(gamma, beta, out);
}

// round 8
// speedup vs baseline: 1.8999x; 1.8999x over previous
#include <cuda_runtime.h>
#include <cstdint>

#define E_N 100000
#define T_N 400000

// Scratch (device globals — no runtime alloc).
__device__ float    g_seg[(long long)E_N * 128];
__device__ float    g_cnt[E_N];
__device__ uint32_t g_fe[(long long)E_N * 128];   // f_edge pre-rounded to tf32
__device__ uint32_t g_Wc[384 * 128];              // W pre-rounded to tf32

// ---------------------------------------------------------------------------
// helpers
// ---------------------------------------------------------------------------
__device__ __forceinline__ uint32_t f2tf(float f) {
    uint32_t o;
    asm("cvt.rna.tf32.f32 %0, %1;" : "=r"(o) : "f"(f));
    return o;
}

__device__ __forceinline__ void mma8(float c[4], const uint32_t a[4],
                                     uint32_t b0, uint32_t b1) {
    asm volatile(
        "mma.sync.aligned.m16n8k8.row.col.f32.tf32.tf32.f32 "
        "{%0,%1,%2,%3}, {%4,%5,%6,%7}, {%8,%9}, {%0,%1,%2,%3};\n"
        : "+f"(c[0]), "+f"(c[1]), "+f"(c[2]), "+f"(c[3])
        : "r"(a[0]), "r"(a[1]), "r"(a[2]), "r"(a[3]), "r"(b0), "r"(b1));
}

__device__ __forceinline__ void red2(float* p, float x, float y) {
    asm volatile("red.global.add.v2.f32 [%0], {%1,%2};"
                 :: "l"(p), "f"(x), "f"(y) : "memory");
}

__device__ __forceinline__ float gelu_exact(float x) {
    return 0.5f * x * (1.0f + erff(x * 0.70710678118654752f));
}

__device__ __forceinline__ void cpa16(uint32_t dst_smem, const void* src) {
    asm volatile("cp.async.cg.shared.global [%0], [%1], 16;"
                 :: "r"(dst_smem), "l"(src));
}

// ---------------------------------------------------------------------------
// kernel 0: fused init — tf32-convert f_edge & W, zero g_seg / g_cnt
// grid 12500 x 256: i in [0, 3.2M) handles one float4
// ---------------------------------------------------------------------------
__global__ void init_kernel(const float* __restrict__ fe,
                            const float* __restrict__ W) {
    int i = blockIdx.x * 256 + threadIdx.x;
    float4 v = ((const float4*)fe)[i];
    uint4 o;
    o.x = f2tf(v.x); o.y = f2tf(v.y); o.z = f2tf(v.z); o.w = f2tf(v.w);
    ((uint4*)g_fe)[i] = o;
    ((float4*)g_seg)[i] = make_float4(0.f, 0.f, 0.f, 0.f);
    if (i < 12288) {                                  // 384*128/4
        float4 w = ((const float4*)W)[i];
        uint4 ow;
        ow.x = f2tf(w.x); ow.y = f2tf(w.y); ow.z = f2tf(w.z); ow.w = f2tf(w.w);
        ((uint4*)g_Wc)[i] = ow;
    }
    if (i < E_N) g_cnt[i] = 0.0f;
}

// ---------------------------------------------------------------------------
// kernel 1: gather + tf32 GEMM (cp.async double-buffered) + GELU + scatter
//   BM=128, BN=128, BK=16, 24 chunks. 8 warps 4(M)x2(N), warp tile 32x64.
// ---------------------------------------------------------------------------
__global__ __launch_bounds__(256, 2)
void tri_gemm_kernel(const float* __restrict__ bias,
                     const int* __restrict__ tri) {
    __shared__ int      sIdx[384];           // [128][3]
    __shared__ float    sBias[128];
    __shared__ uint32_t sA[2][128 * 20];     // 128 rows x 16 k, stride 20
    __shared__ uint32_t sB[2][16 * 136];     // 16 k x 128 n, stride 136

    const int tid = threadIdx.x;
    const int t0  = blockIdx.x * 128;        // T = 3125 * 128

    for (int i = tid; i < 384; i += 256) sIdx[i] = tri[(long long)t0 * 3 + i];
    if (tid < 128) sBias[tid] = bias[tid];
    __syncthreads();

    if (tid < 128) atomicAdd(&g_cnt[sIdx[tid * 3 + 2]], 1.0f);

    const int lane  = tid & 31;
    const int warp  = tid >> 5;
    const int warpM = warp & 3;
    const int warpN = warp >> 2;
    const int gid   = lane >> 2;
    const int t4    = lane & 3;

    // per-thread cp.async mapping (2 x 16B for A, 2 x 16B for B per chunk)
    const int ra0 = tid >> 2;                // A row for i=0   (0..63)
    const int ra1 = ra0 + 64;                // A row for i=1
    const int qa  = (tid & 3) * 4;           // A k-offset (floats)
    const int rb0 = tid >> 5;                // B row i=0 (0..7)
    const int rb1 = rb0 + 8;                 // B row i=1
    const int qb  = (tid & 31) * 4;          // B n-offset (floats)

    const uint32_t sA0 = (uint32_t)__cvta_generic_to_shared(&sA[0][0]);
    const uint32_t sA1 = (uint32_t)__cvta_generic_to_shared(&sA[1][0]);
    const uint32_t sB0 = (uint32_t)__cvta_generic_to_shared(&sB[0][0]);
    const uint32_t sB1 = (uint32_t)__cvta_generic_to_shared(&sB[1][0]);

    float acc[2][8][4];
#pragma unroll
    for (int a = 0; a < 2; ++a)
#pragma unroll
        for (int b = 0; b < 8; ++b)
#pragma unroll
            for (int c = 0; c < 4; ++c) acc[a][b][c] = 0.0f;

    auto load_chunk = [&](int ch, int buf) {
        const int j   = ch >> 3;             // edge slot 0..2
        const int off = (ch & 7) * 16;       // k-offset within edge row
        const uint32_t aBase = buf ? sA1 : sA0;
        const uint32_t bBase = buf ? sB1 : sB0;
        cpa16(aBase + (ra0 * 20 + qa) * 4,
              g_fe + (long long)sIdx[ra0 * 3 + j] * 128 + off + qa);
        cpa16(aBase + (ra1 * 20 + qa) * 4,
              g_fe + (long long)sIdx[ra1 * 3 + j] * 128 + off + qa);
        cpa16(bBase + (rb0 * 136 + qb) * 4, g_Wc + (ch * 16 + rb0) * 128 + qb);
        cpa16(bBase + (rb1 * 136 + qb) * 4, g_Wc + (ch * 16 + rb1) * 128 + qb);
        asm volatile("cp.async.commit_group;" ::: "memory");
    };

    load_chunk(0, 0);

#pragma unroll
    for (int ch = 0; ch < 24; ++ch) {
        const int cur = ch & 1;
        if (ch < 23) {
            load_chunk(ch + 1, cur ^ 1);
            asm volatile("cp.async.wait_group 1;" ::: "memory");
        } else {
            asm volatile("cp.async.wait_group 0;" ::: "memory");
        }
        __syncthreads();

        const uint32_t* A = sA[cur];
        const uint32_t* B = sB[cur];
#pragma unroll
        for (int kk = 0; kk < 2; ++kk) {
            const int k0 = kk * 8;
            uint32_t afr[2][4];
#pragma unroll
            for (int mt = 0; mt < 2; ++mt) {
                int rb = warpM * 32 + mt * 16 + gid;
                afr[mt][0] = A[rb * 20 + k0 + t4];
                afr[mt][1] = A[(rb + 8) * 20 + k0 + t4];
                afr[mt][2] = A[rb * 20 + k0 + t4 + 4];
                afr[mt][3] = A[(rb + 8) * 20 + k0 + t4 + 4];
            }
#pragma unroll
            for (int nt = 0; nt < 8; ++nt) {
                int nb = warpN * 64 + nt * 8 + gid;
                uint32_t b0 = B[(k0 + t4) * 136 + nb];
                uint32_t b1 = B[(k0 + t4 + 4) * 136 + nb];
                mma8(acc[0][nt], afr[0], b0, b1);
                mma8(acc[1][nt], afr[1], b0, b1);
            }
        }
        __syncthreads();   // protect buf[cur] before next iter's load overwrites
    }

    // Epilogue: bias + exact GELU + vectorized segment reduction
#pragma unroll
    for (int mt = 0; mt < 2; ++mt) {
        int r0 = warpM * 32 + mt * 16 + gid;
        int dst0 = sIdx[r0 * 3 + 2];
        int dst1 = sIdx[(r0 + 8) * 3 + 2];
        float* p0 = g_seg + (long long)dst0 * 128;
        float* p1 = g_seg + (long long)dst1 * 128;
#pragma unroll
        for (int nt = 0; nt < 8; ++nt) {
            int c0 = warpN * 64 + nt * 8 + t4 * 2;
            float bv0 = sBias[c0], bv1 = sBias[c0 + 1];
            float x0 = gelu_exact(acc[mt][nt][0] + bv0);
            float x1 = gelu_exact(acc[mt][nt][1] + bv1);
            float x2 = gelu_exact(acc[mt][nt][2] + bv0);
            float x3 = gelu_exact(acc[mt][nt][3] + bv1);
            red2(p0 + c0, x0, x1);
            red2(p1 + c0, x2, x3);
        }
    }
}

// ---------------------------------------------------------------------------
// kernel 2: segment mean + layernorm. One warp per edge.
// ---------------------------------------------------------------------------
__global__ __launch_bounds__(256)
void ln_kernel(const float* __restrict__ gamma,
               const float* __restrict__ beta,
               float* __restrict__ out) {
    const int warp = threadIdx.x >> 5;
    const int lane = threadIdx.x & 31;
    const int e = blockIdx.x * 8 + warp;
    if (e >= E_N) return;

    const float inv = 1.0f / fmaxf(g_cnt[e], 1.0f);
    const long long base = (long long)e * 128;

    float m[4];
    float s = 0.0f;
#pragma unroll
    for (int i = 0; i < 4; ++i) {
        m[i] = g_seg[base + lane + 32 * i] * inv;
        s += m[i];
    }
#pragma unroll
    for (int o = 16; o; o >>= 1) s += __shfl_xor_sync(0xffffffffu, s, o);
    const float mu = s * (1.0f / 128.0f);

    float v = 0.0f;
#pragma unroll
    for (int i = 0; i < 4; ++i) {
        float d = m[i] - mu;
        v += d * d;
    }
#pragma unroll
    for (int o = 16; o; o >>= 1) v += __shfl_xor_sync(0xffffffffu, v, o);
    const float rstd = rsqrtf(v * (1.0f / 128.0f) + 1e-5f);

#pragma unroll
    for (int i = 0; i < 4; ++i) {
        int c = lane + 32 * i;
        out[base + c] = (m[i] - mu) * rstd * gamma[c] + beta[c];
    }
}

// ---------------------------------------------------------------------------
extern "C" void kernel_launch(void* const* d_in, const int* in_sizes, int n_in,
                              void* d_out, int out_size) {
    const float* f_edge = nullptr;
    const float* W      = nullptr;
    const int*   tri    = nullptr;
    const float* vec128[3] = {nullptr, nullptr, nullptr};
    int nv = 0;
    for (int i = 0; i < n_in; ++i) {
        long long sz = in_sizes[i];
        if (sz == (long long)E_N * 128)  f_edge = (const float*)d_in[i];
        else if (sz == 3LL * 128 * 128)  W      = (const float*)d_in[i];
        else if (sz == 3LL * T_N)        tri    = (const int*)d_in[i];
        else if (sz == 128 && nv < 3)    vec128[nv++] = (const float*)d_in[i];
    }
    const float* b     = vec128[0];
    const float* gamma = vec128[1];
    const float* beta  = vec128[2];
    float* out = (float*)d_out;

    init_kernel<<<12500, 256>>>(f_edge, W);
    tri_gemm_kernel<<<T_N / 128, 256>>>(b, tri);
    ln_kernel<<<E_N / 8, 256>>>(gamma, beta, out);
}